// round 13
// baseline (speedup 1.0000x reference)
#include <cuda_runtime.h>
#include <cuda_bf16.h>
#include <mma.h>
#include <math.h>
#include <stdint.h>

using namespace nvcuda;

// ---------------------------------------------------------------------------
// S_Block fused space-time transformer block.
// Round 13: GEMM re-tiled 64x128, 2-stage, 3 CTAs/SM (wave-quantization fix);
//           fuse_b coalesced (warp-per-row).
// ---------------------------------------------------------------------------

#define BB      2
#define TT      4
#define DIMC    768
#define NHEADS  12
#define HDIM    64
#define NPATCH  4096
#define NTOK    4097
#define NS      1025
#define MLPH    3072
#define ROWS_T  (BB*NPATCH)     // 8192
#define ROWS_S  (BB*TT*NS)      // 8200
#define ROWS_O  (BB*NTOK)       // 8194

// ------------------------------ scratch ------------------------------------
__device__ float g_ln  [ROWS_S * DIMC];
__device__ float g_qkv [ROWS_S * 3 * DIMC];
__device__ float g_attn[ROWS_S * DIMC];
__device__ float g_res [ROWS_S * DIMC];
__device__ float g_xt  [ROWS_T * DIMC];
__device__ float g_h   [ROWS_O * MLPH];
__device__ float g_btab[NHEADS * 32 * 32];
#define WR_QKV  0
#define WR_TQKV 1769472
#define WR_PROJ 3538944
#define WR_FC1  4128768
#define WR_FC2  6488064
#define WR_WF   8847360
__device__ float g_wr[9437184];
__device__ float g_bf[DIMC];

// ------------------------------ helpers ------------------------------------
__device__ __forceinline__ float to_tf32(float x) {
    uint32_t r;
    asm("cvt.rna.tf32.f32 %0, %1;" : "=r"(r) : "f"(x));
    return __uint_as_float(r);
}
__device__ __forceinline__ uint32_t smem_u32(const void* p) {
    uint32_t a;
    asm("{ .reg .u64 t; cvta.to.shared.u64 t, %1; cvt.u32.u64 %0, t; }" : "=r"(a) : "l"(p));
    return a;
}
#define CP_ASYNC16(dst, src, nbytes) \
    asm volatile("cp.async.cg.shared.global [%0], [%1], 16, %2;" \
                 :: "r"(dst), "l"(src), "r"(nbytes))
#define CP_COMMIT() asm volatile("cp.async.commit_group;" ::: "memory")
#define CP_WAIT(n)  asm volatile("cp.async.wait_group %0;" :: "n"(n) : "memory")

// ------------------------------ prep kernels -------------------------------
__global__ void round_w_kernel(const float* __restrict__ s, float* __restrict__ d, int n) {
    int i = blockIdx.x * blockDim.x + threadIdx.x;
    if (i < n) d[i] = to_tf32(s[i]);
}

// F[i,j] = sum_k tfc_w[i,k] * tproj_w[k,j]   (768x768x768), tf32-rounded out
__global__ __launch_bounds__(256)
void fuse_w_kernel(const float* __restrict__ tfc_w, const float* __restrict__ tproj_w) {
    __shared__ float At[64][36];
    __shared__ float Bt[32][68];
    int tid = threadIdx.x;
    int tx = tid & 15, ty = tid >> 4;
    int bi0 = blockIdx.y * 64, bj0 = blockIdx.x * 64;
    float acc[4][4];
    #pragma unroll
    for (int i = 0; i < 4; i++)
        #pragma unroll
        for (int j = 0; j < 4; j++) acc[i][j] = 0.f;
    for (int k0 = 0; k0 < DIMC; k0 += 32) {
        #pragma unroll
        for (int it = 0; it < 2; it++) {
            int s = tid * 2 + it;
            int r = s >> 3, c4 = (s & 7) * 4;
            *(float4*)&At[r][c4] = *(const float4*)(tfc_w + (size_t)(bi0 + r) * DIMC + k0 + c4);
        }
        #pragma unroll
        for (int it = 0; it < 2; it++) {
            int s = tid * 2 + it;
            int r = s >> 4, c4 = (s & 15) * 4;
            *(float4*)&Bt[r][c4] = *(const float4*)(tproj_w + (size_t)(k0 + r) * DIMC + bj0 + c4);
        }
        __syncthreads();
        #pragma unroll
        for (int k = 0; k < 32; k++) {
            float a[4], b[4];
            #pragma unroll
            for (int i = 0; i < 4; i++) a[i] = At[ty * 4 + i][k];
            #pragma unroll
            for (int j = 0; j < 4; j++) b[j] = Bt[k][tx * 4 + j];
            #pragma unroll
            for (int i = 0; i < 4; i++)
                #pragma unroll
                for (int j = 0; j < 4; j++) acc[i][j] += a[i] * b[j];
        }
        __syncthreads();
    }
    #pragma unroll
    for (int i = 0; i < 4; i++)
        #pragma unroll
        for (int j = 0; j < 4; j++)
            g_wr[WR_WF + (size_t)(bi0 + ty * 4 + i) * DIMC + bj0 + tx * 4 + j] = to_tf32(acc[i][j]);
}

// g_bf[i] = tfc_b[i] + sum_k tfc_w[i,k] * tproj_b[k]  — warp per row, coalesced
__global__ void fuse_b_kernel(const float* __restrict__ tfc_w, const float* __restrict__ tproj_b,
                              const float* __restrict__ tfc_b) {
    int gw = (blockIdx.x * blockDim.x + threadIdx.x) >> 5;
    int lane = threadIdx.x & 31;
    if (gw >= DIMC) return;
    float s = 0.f;
    for (int k = lane; k < DIMC; k += 32)
        s += tfc_w[(size_t)gw * DIMC + k] * __ldg(&tproj_b[k]);
    #pragma unroll
    for (int o = 16; o > 0; o >>= 1) s += __shfl_xor_sync(0xffffffffu, s, o);
    if (lane == 0) g_bf[gw] = tfc_b[gw] + s;
}

// ------------------------------ WMMA tf32 GEMM -----------------------------
// C[M,N] = act( A[M,K] @ W[N,K]^T + bias ), fp32 in/out, opt +=, opt round.
// Tile 64(M) x 128(N), 8 warps 2x4, warp tile 32x32, K-chunk 32,
// 2-stage cp.async double buffer, 3 CTAs/SM.
#define KC        32
#define AS_STRIDE 36
#define A_STG     (64 * AS_STRIDE)      // 2304 floats
#define B_STG     (128 * AS_STRIDE)     // 4608 floats
#define B_BASE    (2 * A_STG)
#define GEMM_SMEM ((2 * A_STG + 2 * B_STG) * 4)   // 55296 bytes

template<int ACT, int ADD, int RO>
__global__ __launch_bounds__(256, 3)
void wmma_gemm(const float* __restrict__ A, const float* __restrict__ W,
               const float* __restrict__ bias, float* __restrict__ Cout,
               int M, int N, int K) {
    extern __shared__ float smem[];
    uint32_t sb = smem_u32(smem);

    int tid = threadIdx.x;
    int wid = tid >> 5, lane = tid & 31;
    int warp_m = wid & 1;          // 2 groups of 32 rows
    int warp_n = wid >> 1;         // 4 groups of 32 cols
    int bm0 = blockIdx.y * 64, bn0 = blockIdx.x * 128;

    const int nk = K / KC;

    wmma::fragment<wmma::accumulator, 16, 16, 8, float> acc[2][2];
    #pragma unroll
    for (int i = 0; i < 2; i++)
        #pragma unroll
        for (int j = 0; j < 2; j++) wmma::fill_fragment(acc[i][j], 0.0f);

    auto load_chunk = [&](int kc, int st) {
        int k0 = kc * KC + ((tid & 7) * 4);
        // A: 64 rows x 32 cols = 512 float4
        #pragma unroll
        for (int it = 0; it < 2; it++) {
            int s = tid * 2 + it;
            int r = s >> 3 & 63;            // (tid*2+it)>>3 in 0..63
            int c4 = ((s & 7) * 4);
            int ga = bm0 + r;
            int okA = (ga < M) ? 16 : 0;
            const float* srcA = A + (size_t)(okA ? ga : 0) * K + kc * KC + c4;
            uint32_t dA = sb + (uint32_t)(st * A_STG + r * AS_STRIDE + c4) * 4u;
            CP_ASYNC16(dA, srcA, okA);
        }
        // B: 128 rows x 32 cols = 1024 float4
        #pragma unroll
        for (int it = 0; it < 4; it++) {
            int s = tid + it * 256;
            int r = s >> 3;                 // 0..127
            int c4 = (s & 7) * 4;
            const float* srcB = W + (size_t)(bn0 + r) * K + kc * KC + c4;
            uint32_t dB = sb + (uint32_t)(B_BASE + st * B_STG + r * AS_STRIDE + c4) * 4u;
            CP_ASYNC16(dB, srcB, 16);
        }
        CP_COMMIT();
        (void)k0;
    };

    load_chunk(0, 0);
    load_chunk(1, 1);

    for (int kc = 0; kc < nk; kc++) {
        if (kc < nk - 1) CP_WAIT(1); else CP_WAIT(0);
        __syncthreads();

        int st = kc & 1;
        const float* As = smem + st * A_STG;
        const float* Bs = smem + B_BASE + st * B_STG;

        #pragma unroll
        for (int kk = 0; kk < KC; kk += 8) {
            wmma::fragment<wmma::matrix_a, 16, 16, 8, wmma::precision::tf32, wmma::row_major> af[2];
            wmma::fragment<wmma::matrix_b, 16, 16, 8, wmma::precision::tf32, wmma::col_major> bf[2];
            #pragma unroll
            for (int i = 0; i < 2; i++)
                wmma::load_matrix_sync(af[i], As + (warp_m * 32 + i * 16) * AS_STRIDE + kk, AS_STRIDE);
            #pragma unroll
            for (int j = 0; j < 2; j++)
                wmma::load_matrix_sync(bf[j], Bs + (warp_n * 32 + j * 16) * AS_STRIDE + kk, AS_STRIDE);
            #pragma unroll
            for (int i = 0; i < 2; i++)
                #pragma unroll
                for (int j = 0; j < 2; j++)
                    wmma::mma_sync(acc[i][j], af[i], bf[j], acc[i][j]);
        }
        __syncthreads();                      // all reads of this buffer done
        if (kc + 2 < nk) load_chunk(kc + 2, kc & 1);
    }

    // epilogue: per-warp smem staging (aliases stage memory)
    __syncthreads();
    float* ebuf = smem + wid * 320;           // 16 x 20 per warp
    int er = lane >> 1;
    int ec = (lane & 1) * 8;
    #pragma unroll
    for (int i = 0; i < 2; i++) {
        #pragma unroll
        for (int j = 0; j < 2; j++) {
            wmma::store_matrix_sync(ebuf, acc[i][j], 20, wmma::mem_row_major);
            __syncwarp();
            int grow = bm0 + warp_m * 32 + i * 16 + er;
            int col0 = bn0 + warp_n * 32 + j * 16 + ec;
            if (grow < M) {
                float v[8];
                #pragma unroll
                for (int t = 0; t < 8; t++) {
                    float u = ebuf[er * 20 + ec + t];
                    if (bias) u += bias[col0 + t];
                    if (ACT == 1) u = 0.5f * u * (1.0f + erff(u * 0.70710678118654752f));
                    if (RO) u = to_tf32(u);
                    v[t] = u;
                }
                float* op = Cout + (size_t)grow * N + col0;
                if (ADD) {
                    #pragma unroll
                    for (int t = 0; t < 8; t += 4) {
                        float4 o = *(float4*)(op + t);
                        o.x += v[t]; o.y += v[t + 1]; o.z += v[t + 2]; o.w += v[t + 3];
                        *(float4*)(op + t) = o;
                    }
                } else {
                    #pragma unroll
                    for (int t = 0; t < 8; t += 4)
                        *(float4*)(op + t) = make_float4(v[t], v[t + 1], v[t + 2], v[t + 3]);
                }
            }
            __syncwarp();
        }
    }
}

// ------------------------------ layernorm (tf32-rounded out) ---------------
__global__ __launch_bounds__(256)
void ln_kernel(const float* __restrict__ x, const float* __restrict__ io,
               const float* __restrict__ gamma, const float* __restrict__ beta,
               int mode) {
    int row = blockIdx.x;
    const float* src;
    if (mode == 0) {
        int b = row >> 12, j = row & 4095;
        src = x + ((size_t)b * NTOK + 1 + j) * DIMC;
    } else if (mode == 1) {
        int bt = row / NS, i = row - bt * NS;
        int b = bt >> 2, t = bt & 3;
        if (i == 0) src = x + (size_t)b * NTOK * DIMC;
        else        src = g_xt + ((size_t)b * NPATCH + (size_t)(i - 1) * TT + t) * DIMC;
    } else {
        src = io + (size_t)row * DIMC;
    }
    int tid = threadIdx.x;
    float v0 = src[tid], v1 = src[tid + 256], v2 = src[tid + 512];
    float s = v0 + v1 + v2;
    float ss = v0 * v0 + v1 * v1 + v2 * v2;
    #pragma unroll
    for (int o = 16; o > 0; o >>= 1) {
        s  += __shfl_xor_sync(0xffffffffu, s, o);
        ss += __shfl_xor_sync(0xffffffffu, ss, o);
    }
    __shared__ float rs[8], rss[8];
    int w = tid >> 5, lane = tid & 31;
    if (lane == 0) { rs[w] = s; rss[w] = ss; }
    __syncthreads();
    if (w == 0) {
        float a = (lane < 8) ? rs[lane] : 0.f;
        float b2 = (lane < 8) ? rss[lane] : 0.f;
        #pragma unroll
        for (int o = 4; o > 0; o >>= 1) {
            a  += __shfl_xor_sync(0xffffffffu, a, o);
            b2 += __shfl_xor_sync(0xffffffffu, b2, o);
        }
        if (lane == 0) { rs[0] = a; rss[0] = b2; }
    }
    __syncthreads();
    float mean = rs[0] * (1.f / DIMC);
    float var  = rss[0] * (1.f / DIMC) - mean * mean;
    float rstd = rsqrtf(var + 1e-5f);
    float* dst = g_ln + (size_t)row * DIMC;
    dst[tid]       = to_tf32((v0 - mean) * rstd * gamma[tid]       + beta[tid]);
    dst[tid + 256] = to_tf32((v1 - mean) * rstd * gamma[tid + 256] + beta[tid + 256]);
    dst[tid + 512] = to_tf32((v2 - mean) * rstd * gamma[tid + 512] + beta[tid + 512]);
}

// ------------------------------ temporal attention -------------------------
__global__ __launch_bounds__(256)
void temporal_attn_kernel(const float* __restrict__ qkv, float* __restrict__ out) {
    int idx = blockIdx.x * blockDim.x + threadIdx.x;
    if (idx >= (ROWS_T / TT) * NHEADS * TT) return;
    int g = idx / (NHEADS * TT);
    int rem = idx - g * (NHEADS * TT);
    int h = rem >> 2, t = rem & 3;
    size_t base = (size_t)g * TT * (3 * DIMC);
    const float4* qp = (const float4*)(qkv + base + (size_t)t * (3 * DIMC) + h * HDIM);
    float4 q[16];
    #pragma unroll
    for (int i = 0; i < 16; i++) q[i] = qp[i];
    float s[4];
    #pragma unroll
    for (int j = 0; j < 4; j++) {
        const float4* kp = (const float4*)(qkv + base + (size_t)j * (3 * DIMC) + DIMC + h * HDIM);
        float a = 0.f;
        #pragma unroll
        for (int i = 0; i < 16; i++) {
            float4 k = kp[i];
            a += q[i].x * k.x + q[i].y * k.y + q[i].z * k.z + q[i].w * k.w;
        }
        s[j] = a * 0.125f;
    }
    float m = fmaxf(fmaxf(s[0], s[1]), fmaxf(s[2], s[3]));
    float p[4], l = 0.f;
    #pragma unroll
    for (int j = 0; j < 4; j++) { p[j] = __expf(s[j] - m); l += p[j]; }
    float inv = 1.f / l;
    #pragma unroll
    for (int j = 0; j < 4; j++) p[j] *= inv;
    const float4* v0 = (const float4*)(qkv + base + 0 * (3 * DIMC) + 2 * DIMC + h * HDIM);
    const float4* v1 = (const float4*)(qkv + base + 1 * (3 * DIMC) + 2 * DIMC + h * HDIM);
    const float4* v2 = (const float4*)(qkv + base + 2 * (3 * DIMC) + 2 * DIMC + h * HDIM);
    const float4* v3 = (const float4*)(qkv + base + 3 * (3 * DIMC) + 2 * DIMC + h * HDIM);
    float4* op = (float4*)(out + ((size_t)g * TT + t) * DIMC + h * HDIM);
    #pragma unroll
    for (int i = 0; i < 16; i++) {
        float4 a = v0[i], b = v1[i], c = v2[i], d = v3[i];
        float4 o;
        o.x = to_tf32(p[0]*a.x + p[1]*b.x + p[2]*c.x + p[3]*d.x);
        o.y = to_tf32(p[0]*a.y + p[1]*b.y + p[2]*c.y + p[3]*d.y);
        o.z = to_tf32(p[0]*a.z + p[1]*b.z + p[2]*c.z + p[3]*d.z);
        o.w = to_tf32(p[0]*a.w + p[1]*b.w + p[2]*c.w + p[3]*d.w);
        op[i] = o;
    }
}

// ------------------------------ geometry bias LUT --------------------------
__global__ void bias_table_kernel(const float* __restrict__ wg_w,
                                  const float* __restrict__ wg_b) {
    int h = blockIdx.x;
    int tid = threadIdx.x;
    int dr = tid >> 5, dc = tid & 31;
    const float* w = wg_w + h * 64;
    float vx = fabsf(((float)dr / 32.0f) / 1.03125f);
    float vy = fabsf(((float)dc / 32.0f) / 1.03125f);
    float dx = logf(fmaxf(vx, 0.001f));
    float dy = logf(fmaxf(vy, 0.001f));
    float acc = wg_b[h];
    #pragma unroll
    for (int mm = 48; mm < 64; mm++) acc += w[mm];
    #pragma unroll
    for (int mm = 0; mm < 8; mm++) {
        float dm = powf(1000.0f, -(float)mm / 8.0f);
        float ax = 100.f * dx * dm;
        float ay = 100.f * dy * dm;
        acc += sinf(ax) * w[mm] + sinf(ay) * w[8 + mm]
             + cosf(ax) * w[32 + mm] + cosf(ay) * w[40 + mm];
    }
    float ww = fmaxf(acc, 0.f);
    g_btab[h * 1024 + tid] = logf(fmaxf(ww, 1e-6f));
}

// ------------------------------ spatial attention (tf32 WMMA) --------------
#define SQ_LD   72
#define SATT_Q  0
#define SATT_K  (128 * SQ_LD)
#define SATT_V  (SATT_K + 64 * SQ_LD)
#define SATT_S  (SATT_V + 64 * SQ_LD)
#define SATT_L  (SATT_S + 128 * SQ_LD)
#define SATT_SMEM ((SATT_L + 128) * 4)      // 111104 bytes
#define NKT     ((NS + 63) / 64)            // 17

__global__ __launch_bounds__(256, 2)
void spatial_attn_wmma(const float* __restrict__ qkv, float* __restrict__ out) {
    extern __shared__ float sm[];
    float* Qs = sm + SATT_Q;
    float* Ks = sm + SATT_K;
    float* Vs = sm + SATT_V;
    float* Sp = sm + SATT_S;
    float* Lw = sm + SATT_L;

    int bh = blockIdx.x;
    int bt = bh / NHEADS, h = bh - bt * NHEADS;
    int tid = threadIdx.x, wid = tid >> 5;
    int qbase = blockIdx.y * 128;

    for (int i = tid; i < 128 * 16; i += 256) {
        int r = i >> 4, c4 = (i & 15) * 4;
        int qi = qbase + r;
        float4 v = make_float4(0.f, 0.f, 0.f, 0.f);
        if (qi < NS)
            v = *(const float4*)(qkv + ((size_t)bt * NS + qi) * (3 * DIMC) + h * HDIM + c4);
        v.x *= 0.125f; v.y *= 0.125f; v.z *= 0.125f; v.w *= 0.125f;
        *(float4*)&Qs[r * SQ_LD + c4] = v;
    }
    if (tid < 128) Lw[tid] = 0.f;

    int myrow = tid >> 1;
    int mycol = (tid & 1) * 32;
    int qi_own = qbase + myrow;
    bool qvalid = qi_own < NS;
    int brow = 0, bcol = 0;
    if (qvalid && qi_own > 0) { brow = (qi_own - 1) >> 5; bcol = (qi_own - 1) & 31; }
    const float* btab_h = g_btab + h * 1024;

    wmma::fragment<wmma::accumulator, 16, 16, 8, float> oacc[4];
    #pragma unroll
    for (int j = 0; j < 4; j++) wmma::fill_fragment(oacc[j], 0.0f);

    for (int kt = 0; kt < NKT; kt++) {
        int k0 = kt * 64;
        __syncthreads();
        for (int i = tid; i < 64 * 16; i += 256) {
            int r = i >> 4, c4 = (i & 15) * 4;
            int jj = k0 + r;
            float4 kv = make_float4(0.f, 0.f, 0.f, 0.f);
            float4 vv = make_float4(0.f, 0.f, 0.f, 0.f);
            if (jj < NS) {
                const float* base = qkv + ((size_t)bt * NS + jj) * (3 * DIMC) + h * HDIM + c4;
                kv = *(const float4*)(base + DIMC);
                vv = *(const float4*)(base + 2 * DIMC);
            }
            *(float4*)&Ks[r * SQ_LD + c4] = kv;
            *(float4*)&Vs[r * SQ_LD + c4] = vv;
        }
        __syncthreads();

        // S = Q @ K^T
        {
            wmma::fragment<wmma::accumulator, 16, 16, 8, float> sacc[4];
            #pragma unroll
            for (int j = 0; j < 4; j++) wmma::fill_fragment(sacc[j], 0.0f);
            #pragma unroll
            for (int ks = 0; ks < 8; ks++) {
                wmma::fragment<wmma::matrix_a, 16, 16, 8, wmma::precision::tf32, wmma::row_major> af;
                wmma::load_matrix_sync(af, Qs + (wid * 16) * SQ_LD + ks * 8, SQ_LD);
                #pragma unroll
                for (int j = 0; j < 4; j++) {
                    wmma::fragment<wmma::matrix_b, 16, 16, 8, wmma::precision::tf32, wmma::col_major> bf;
                    wmma::load_matrix_sync(bf, Ks + (j * 16) * SQ_LD + ks * 8, SQ_LD);
                    wmma::mma_sync(sacc[j], af, bf, sacc[j]);
                }
            }
            #pragma unroll
            for (int j = 0; j < 4; j++)
                wmma::store_matrix_sync(Sp + (wid * 16) * SQ_LD + j * 16, sacc[j], SQ_LD, wmma::mem_row_major);
        }
        __syncthreads();

        // P = exp(S + bias); row-sum into Lw; P stored tf32-rounded
        {
            float* srow = Sp + myrow * SQ_LD + mycol;
            float part = 0.f;
            if (qvalid) {
                #pragma unroll
                for (int c = 0; c < 32; c++) {
                    int jj = k0 + mycol + c;
                    float p = 0.f;
                    if (jj < NS) {
                        float s = srow[c];
                        if (qi_own > 0 && jj > 0) {
                            int jr = (jj - 1) >> 5, jc = (jj - 1) & 31;
                            int dr = brow - jr; dr = dr < 0 ? -dr : dr;
                            int dc = bcol - jc; dc = dc < 0 ? -dc : dc;
                            s += __ldg(&btab_h[dr * 32 + dc]);
                        }
                        p = __expf(s);
                    }
                    srow[c] = to_tf32(p);
                    part += p;
                }
            } else {
                #pragma unroll
                for (int c = 0; c < 32; c++) srow[c] = 0.f;
            }
            part += __shfl_xor_sync(0xffffffffu, part, 1);
            if ((tid & 1) == 0) Lw[myrow] += part;
        }
        __syncthreads();

        // O += P @ V
        #pragma unroll
        for (int ks = 0; ks < 8; ks++) {
            wmma::fragment<wmma::matrix_a, 16, 16, 8, wmma::precision::tf32, wmma::row_major> af;
            wmma::load_matrix_sync(af, Sp + (wid * 16) * SQ_LD + ks * 8, SQ_LD);
            #pragma unroll
            for (int j = 0; j < 4; j++) {
                wmma::fragment<wmma::matrix_b, 16, 16, 8, wmma::precision::tf32, wmma::row_major> bf;
                wmma::load_matrix_sync(bf, Vs + (ks * 8) * SQ_LD + j * 16, SQ_LD);
                wmma::mma_sync(oacc[j], af, bf, oacc[j]);
            }
        }
    }

    __syncthreads();
    #pragma unroll
    for (int j = 0; j < 4; j++)
        wmma::store_matrix_sync(Sp + (wid * 16) * SQ_LD + j * 16, oacc[j], SQ_LD, wmma::mem_row_major);
    __syncthreads();

    if (qvalid) {
        float inv = 1.f / Lw[myrow];
        const float* srow = Sp + myrow * SQ_LD + mycol;
        float* op = out + ((size_t)bt * NS + qi_own) * DIMC + h * HDIM + mycol;
        #pragma unroll
        for (int c = 0; c < 32; c += 4) {
            float4 v = *(const float4*)(srow + c);
            v.x = to_tf32(v.x * inv); v.y = to_tf32(v.y * inv);
            v.z = to_tf32(v.z * inv); v.w = to_tf32(v.w * inv);
            *(float4*)(op + c) = v;
        }
    }
}

// ------------------------------ elementwise --------------------------------
__global__ void copy_xt_kernel(const float* __restrict__ x) {
    int idx = blockIdx.x * blockDim.x + threadIdx.x;
    if (idx >= ROWS_T * DIMC) return;
    int row = idx / DIMC, d = idx - row * DIMC;
    int b = row >> 12, j = row & 4095;
    g_xt[idx] = x[((size_t)b * NTOK + 1 + j) * DIMC + d];
}

__global__ void combine_kernel(const float* __restrict__ x, float* __restrict__ out) {
    int idx = blockIdx.x * blockDim.x + threadIdx.x;
    if (idx >= ROWS_O * DIMC) return;
    int row = idx / DIMC, d = idx - row * DIMC;
    int b = row / NTOK, tok = row - b * NTOK;
    float v;
    if (tok == 0) {
        float s = 0.f;
        #pragma unroll
        for (int t = 0; t < TT; t++)
            s += g_res[((size_t)(b * TT + t) * NS + 0) * DIMC + d];
        v = x[idx] + 0.25f * s;
    } else {
        int p = tok - 1;
        int hw = p >> 2, t = p & 3;
        v = g_xt[((size_t)b * NPATCH + p) * DIMC + d]
          + g_res[((size_t)(b * TT + t) * NS + 1 + hw) * DIMC + d];
    }
    out[idx] = v;
}

// ------------------------------ launch -------------------------------------
extern "C" void kernel_launch(void* const* d_in, const int* in_sizes, int n_in,
                              void* d_out, int out_size) {
    const float* x       = (const float*)d_in[0];
    const float* norm1_g = (const float*)d_in[1];
    const float* norm1_b = (const float*)d_in[2];
    const float* qkv_w   = (const float*)d_in[3];
    const float* proj_w  = (const float*)d_in[4];
    const float* proj_b  = (const float*)d_in[5];
    const float* wg_w    = (const float*)d_in[6];
    const float* wg_b    = (const float*)d_in[7];
    const float* tnorm1_g= (const float*)d_in[8];
    const float* tnorm1_b= (const float*)d_in[9];
    const float* tqkv_w  = (const float*)d_in[10];
    const float* tproj_w = (const float*)d_in[11];
    const float* tproj_b = (const float*)d_in[12];
    const float* tfc_w   = (const float*)d_in[13];
    const float* tfc_b   = (const float*)d_in[14];
    const float* norm2_g = (const float*)d_in[15];
    const float* norm2_b = (const float*)d_in[16];
    const float* fc1_w   = (const float*)d_in[17];
    const float* fc1_b   = (const float*)d_in[18];
    const float* fc2_w   = (const float*)d_in[19];
    const float* fc2_b   = (const float*)d_in[20];
    float* out = (float*)d_out;

    float *p_ln, *p_qkv, *p_attn, *p_res, *p_xt, *p_h, *p_wr, *p_bf;
    cudaGetSymbolAddress((void**)&p_ln,   g_ln);
    cudaGetSymbolAddress((void**)&p_qkv,  g_qkv);
    cudaGetSymbolAddress((void**)&p_attn, g_attn);
    cudaGetSymbolAddress((void**)&p_res,  g_res);
    cudaGetSymbolAddress((void**)&p_xt,   g_xt);
    cudaGetSymbolAddress((void**)&p_h,    g_h);
    cudaGetSymbolAddress((void**)&p_wr,   g_wr);
    cudaGetSymbolAddress((void**)&p_bf,   g_bf);

    cudaFuncSetAttribute(wmma_gemm<0,0,0>, cudaFuncAttributeMaxDynamicSharedMemorySize, GEMM_SMEM);
    cudaFuncSetAttribute(wmma_gemm<0,0,1>, cudaFuncAttributeMaxDynamicSharedMemorySize, GEMM_SMEM);
    cudaFuncSetAttribute(wmma_gemm<0,1,0>, cudaFuncAttributeMaxDynamicSharedMemorySize, GEMM_SMEM);
    cudaFuncSetAttribute(wmma_gemm<1,0,1>, cudaFuncAttributeMaxDynamicSharedMemorySize, GEMM_SMEM);
    cudaFuncSetAttribute(spatial_attn_wmma, cudaFuncAttributeMaxDynamicSharedMemorySize, SATT_SMEM);

    // ---- prep: round weights to tf32, fuse tfc∘tproj ----
    round_w_kernel<<<(1769472+255)/256, 256>>>(qkv_w,  p_wr + WR_QKV,  1769472);
    round_w_kernel<<<(1769472+255)/256, 256>>>(tqkv_w, p_wr + WR_TQKV, 1769472);
    round_w_kernel<<<(589824+255)/256, 256>>>(proj_w,  p_wr + WR_PROJ, 589824);
    round_w_kernel<<<(2359296+255)/256, 256>>>(fc1_w,  p_wr + WR_FC1,  2359296);
    round_w_kernel<<<(2359296+255)/256, 256>>>(fc2_w,  p_wr + WR_FC2,  2359296);
    fuse_w_kernel<<<dim3(12, 12), 256>>>(tfc_w, tproj_w);
    fuse_b_kernel<<<96, 256>>>(tfc_w, tproj_b, tfc_b);

    // ---- temporal branch ----  (M tiles of 64)
    ln_kernel<<<ROWS_T, 256>>>(x, nullptr, tnorm1_g, tnorm1_b, 0);
    wmma_gemm<0,0,1><<<dim3(18, 128), 256, GEMM_SMEM>>>(p_ln, p_wr + WR_TQKV, nullptr, p_qkv, ROWS_T, 3*DIMC, DIMC);
    temporal_attn_kernel<<<(ROWS_T * NHEADS + 255) / 256, 256>>>(p_qkv, p_attn);
    copy_xt_kernel<<<(ROWS_T * DIMC + 255) / 256, 256>>>(x);
    wmma_gemm<0,1,0><<<dim3(6, 128), 256, GEMM_SMEM>>>(p_attn, p_wr + WR_WF, p_bf, p_xt, ROWS_T, DIMC, DIMC);

    // ---- spatial branch ----
    ln_kernel<<<ROWS_S, 256>>>(x, nullptr, norm1_g, norm1_b, 1);
    wmma_gemm<0,0,1><<<dim3(18, 129), 256, GEMM_SMEM>>>(p_ln, p_wr + WR_QKV, nullptr, p_qkv, ROWS_S, 3*DIMC, DIMC);
    bias_table_kernel<<<NHEADS, 1024>>>(wg_w, wg_b);
    spatial_attn_wmma<<<dim3(BB*TT*NHEADS, (NS + 127) / 128), 256, SATT_SMEM>>>(p_qkv, p_attn);
    wmma_gemm<0,0,0><<<dim3(6, 129), 256, GEMM_SMEM>>>(p_attn, p_wr + WR_PROJ, proj_b, p_res, ROWS_S, DIMC, DIMC);
    combine_kernel<<<(ROWS_O * DIMC + 255) / 256, 256>>>(x, out);

    // ---- MLP ----
    ln_kernel<<<ROWS_O, 256>>>(nullptr, out, norm2_g, norm2_b, 2);
    wmma_gemm<1,0,1><<<dim3(24, 129), 256, GEMM_SMEM>>>(p_ln, p_wr + WR_FC1, fc1_b, p_h, ROWS_O, MLPH, DIMC);
    wmma_gemm<0,1,0><<<dim3(6, 129), 256, GEMM_SMEM>>>(p_h, p_wr + WR_FC2, fc2_b, out, ROWS_O, DIMC, MLPH);
}

// round 14
// speedup vs baseline: 1.1041x; 1.1041x over previous
#include <cuda_runtime.h>
#include <cuda_bf16.h>
#include <mma.h>
#include <math.h>
#include <stdint.h>

using namespace nvcuda;

// ---------------------------------------------------------------------------
// S_Block fused space-time transformer block.
// Round 14: R12 GEMM (128x128, 3-stage, 1 barrier) restored; prep de-taxed
//           (fuse_b warp-per-row; fuse_w on tensor cores via transpose).
// ---------------------------------------------------------------------------

#define BB      2
#define TT      4
#define DIMC    768
#define NHEADS  12
#define HDIM    64
#define NPATCH  4096
#define NTOK    4097
#define NS      1025
#define MLPH    3072
#define ROWS_T  (BB*NPATCH)     // 8192
#define ROWS_S  (BB*TT*NS)      // 8200
#define ROWS_O  (BB*NTOK)       // 8194

// ------------------------------ scratch ------------------------------------
__device__ float g_ln  [ROWS_S * DIMC];
__device__ float g_qkv [ROWS_S * 3 * DIMC];
__device__ float g_attn[ROWS_S * DIMC];
__device__ float g_res [ROWS_S * DIMC];
__device__ float g_xt  [ROWS_T * DIMC];
__device__ float g_h   [ROWS_O * MLPH];     // also prep scratch (pre-fc1)
__device__ float g_btab[NHEADS * 32 * 32];
#define WR_QKV  0
#define WR_TQKV 1769472
#define WR_PROJ 3538944
#define WR_FC1  4128768
#define WR_FC2  6488064
#define WR_WF   8847360
__device__ float g_wr[9437184];
__device__ float g_bf[DIMC];

// ------------------------------ helpers ------------------------------------
__device__ __forceinline__ float to_tf32(float x) {
    uint32_t r;
    asm("cvt.rna.tf32.f32 %0, %1;" : "=r"(r) : "f"(x));
    return __uint_as_float(r);
}
__device__ __forceinline__ uint32_t smem_u32(const void* p) {
    uint32_t a;
    asm("{ .reg .u64 t; cvta.to.shared.u64 t, %1; cvt.u32.u64 %0, t; }" : "=r"(a) : "l"(p));
    return a;
}
#define CP_ASYNC16(dst, src, nbytes) \
    asm volatile("cp.async.cg.shared.global [%0], [%1], 16, %2;" \
                 :: "r"(dst), "l"(src), "r"(nbytes))
#define CP_COMMIT() asm volatile("cp.async.commit_group;" ::: "memory")
#define CP_WAIT(n)  asm volatile("cp.async.wait_group %0;" :: "n"(n) : "memory")

// ------------------------------ prep kernels -------------------------------
__global__ void round_w_kernel(const float* __restrict__ s, float* __restrict__ d, int n) {
    int i = blockIdx.x * blockDim.x + threadIdx.x;
    if (i < n) d[i] = to_tf32(s[i]);
}

// dst = tf32-round(src^T), 768x768, 32x32 tiles
__global__ __launch_bounds__(256)
void transpose_round_kernel(const float* __restrict__ src, float* __restrict__ dst) {
    __shared__ float t[32][33];
    int bx0 = blockIdx.x * 32, by0 = blockIdx.y * 32;
    int tx = threadIdx.x, ty = threadIdx.y;      // 32 x 8
    #pragma unroll
    for (int i = 0; i < 32; i += 8)
        t[ty + i][tx] = src[(size_t)(by0 + ty + i) * DIMC + bx0 + tx];
    __syncthreads();
    #pragma unroll
    for (int i = 0; i < 32; i += 8)
        dst[(size_t)(bx0 + ty + i) * DIMC + by0 + tx] = to_tf32(t[tx][ty + i]);
}

// g_bf[i] = tfc_b[i] + sum_k tfc_w[i,k] * tproj_b[k]  — warp per row, coalesced
__global__ void fuse_b_kernel(const float* __restrict__ tfc_w, const float* __restrict__ tproj_b,
                              const float* __restrict__ tfc_b) {
    int gw = (blockIdx.x * blockDim.x + threadIdx.x) >> 5;
    int lane = threadIdx.x & 31;
    if (gw >= DIMC) return;
    float s = 0.f;
    for (int k = lane; k < DIMC; k += 32)
        s += tfc_w[(size_t)gw * DIMC + k] * __ldg(&tproj_b[k]);
    #pragma unroll
    for (int o = 16; o > 0; o >>= 1) s += __shfl_xor_sync(0xffffffffu, s, o);
    if (lane == 0) g_bf[gw] = tfc_b[gw] + s;
}

// ------------------------------ WMMA tf32 GEMM -----------------------------
// C[M,N] = act( A[M,K] @ W[N,K]^T + bias ), fp32 in/out, opt +=, opt round.
// 128x128 tile, 8 warps 2x4, warp tile 64x32, K-chunk 32,
// depth-2 pipeline over 3 buffers (1 barrier/chunk), 2 CTAs/SM.
#define KC        32
#define AS_STRIDE 36
#define STAGE_F   (128 * AS_STRIDE)
#define NSTAGE    3
#define B_OFF     (NSTAGE * STAGE_F)
#define GEMM_SMEM (2 * NSTAGE * STAGE_F * 4)   // 110592 bytes

template<int ACT, int ADD, int RO>
__global__ __launch_bounds__(256, 2)
void wmma_gemm(const float* __restrict__ A, const float* __restrict__ W,
               const float* __restrict__ bias, float* __restrict__ Cout,
               int M, int N, int K) {
    extern __shared__ float smem[];
    uint32_t sb = smem_u32(smem);

    int tid = threadIdx.x;
    int wid = tid >> 5, lane = tid & 31;
    int warp_m = wid & 1;
    int warp_n = wid >> 1;
    int bm0 = blockIdx.y * 128, bn0 = blockIdx.x * 128;

    int lr = tid >> 3;
    int lc = (tid & 7) * 4;

    const int nk = K / KC;

    wmma::fragment<wmma::accumulator, 16, 16, 8, float> acc[4][2];
    #pragma unroll
    for (int i = 0; i < 4; i++)
        #pragma unroll
        for (int j = 0; j < 2; j++) wmma::fill_fragment(acc[i][j], 0.0f);

    auto load_chunk = [&](int kc, int st) {
        int k0 = kc * KC + lc;
        #pragma unroll
        for (int it = 0; it < 4; it++) {
            int row = lr + it * 32;
            int ga = bm0 + row;
            int okA = (ga < M) ? 16 : 0;
            const float* srcA = A + (size_t)(okA ? ga : 0) * K + k0;
            uint32_t dA = sb + (uint32_t)(st * STAGE_F + row * AS_STRIDE + lc) * 4u;
            CP_ASYNC16(dA, srcA, okA);
            const float* srcB = W + (size_t)(bn0 + row) * K + k0;
            uint32_t dB = sb + (uint32_t)(B_OFF + st * STAGE_F + row * AS_STRIDE + lc) * 4u;
            CP_ASYNC16(dB, srcB, 16);
        }
        CP_COMMIT();
    };

    load_chunk(0, 0);
    load_chunk(1, 1);

    for (int kc = 0; kc < nk; kc++) {
        if (kc < nk - 1) CP_WAIT(1); else CP_WAIT(0);
        __syncthreads();

        int st = kc % NSTAGE;
        const float* As = smem + st * STAGE_F;
        const float* Bs = smem + B_OFF + st * STAGE_F;

        #pragma unroll
        for (int kk = 0; kk < KC; kk += 8) {
            wmma::fragment<wmma::matrix_a, 16, 16, 8, wmma::precision::tf32, wmma::row_major> af[4];
            wmma::fragment<wmma::matrix_b, 16, 16, 8, wmma::precision::tf32, wmma::col_major> bf[2];
            #pragma unroll
            for (int i = 0; i < 4; i++)
                wmma::load_matrix_sync(af[i], As + (warp_m * 64 + i * 16) * AS_STRIDE + kk, AS_STRIDE);
            #pragma unroll
            for (int j = 0; j < 2; j++)
                wmma::load_matrix_sync(bf[j], Bs + (warp_n * 32 + j * 16) * AS_STRIDE + kk, AS_STRIDE);
            #pragma unroll
            for (int i = 0; i < 4; i++)
                #pragma unroll
                for (int j = 0; j < 2; j++)
                    wmma::mma_sync(acc[i][j], af[i], bf[j], acc[i][j]);
        }
        if (kc + 2 < nk) load_chunk(kc + 2, (kc + 2) % NSTAGE);
    }

    __syncthreads();
    float* ebuf = smem + wid * 320;
    int er = lane >> 1;
    int ec = (lane & 1) * 8;
    #pragma unroll
    for (int i = 0; i < 4; i++) {
        #pragma unroll
        for (int j = 0; j < 2; j++) {
            wmma::store_matrix_sync(ebuf, acc[i][j], 20, wmma::mem_row_major);
            __syncwarp();
            int grow = bm0 + warp_m * 64 + i * 16 + er;
            int col0 = bn0 + warp_n * 32 + j * 16 + ec;
            if (grow < M) {
                float v[8];
                #pragma unroll
                for (int t = 0; t < 8; t++) {
                    float u = ebuf[er * 20 + ec + t];
                    if (bias) u += bias[col0 + t];
                    if (ACT == 1) u = 0.5f * u * (1.0f + erff(u * 0.70710678118654752f));
                    if (RO) u = to_tf32(u);
                    v[t] = u;
                }
                float* op = Cout + (size_t)grow * N + col0;
                if (ADD) {
                    #pragma unroll
                    for (int t = 0; t < 8; t += 4) {
                        float4 o = *(float4*)(op + t);
                        o.x += v[t]; o.y += v[t + 1]; o.z += v[t + 2]; o.w += v[t + 3];
                        *(float4*)(op + t) = o;
                    }
                } else {
                    #pragma unroll
                    for (int t = 0; t < 8; t += 4)
                        *(float4*)(op + t) = make_float4(v[t], v[t + 1], v[t + 2], v[t + 3]);
                }
            }
            __syncwarp();
        }
    }
}

// ------------------------------ layernorm (tf32-rounded out) ---------------
__global__ __launch_bounds__(256)
void ln_kernel(const float* __restrict__ x, const float* __restrict__ io,
               const float* __restrict__ gamma, const float* __restrict__ beta,
               int mode) {
    int row = blockIdx.x;
    const float* src;
    if (mode == 0) {
        int b = row >> 12, j = row & 4095;
        src = x + ((size_t)b * NTOK + 1 + j) * DIMC;
    } else if (mode == 1) {
        int bt = row / NS, i = row - bt * NS;
        int b = bt >> 2, t = bt & 3;
        if (i == 0) src = x + (size_t)b * NTOK * DIMC;
        else        src = g_xt + ((size_t)b * NPATCH + (size_t)(i - 1) * TT + t) * DIMC;
    } else {
        src = io + (size_t)row * DIMC;
    }
    int tid = threadIdx.x;
    float v0 = src[tid], v1 = src[tid + 256], v2 = src[tid + 512];
    float s = v0 + v1 + v2;
    float ss = v0 * v0 + v1 * v1 + v2 * v2;
    #pragma unroll
    for (int o = 16; o > 0; o >>= 1) {
        s  += __shfl_xor_sync(0xffffffffu, s, o);
        ss += __shfl_xor_sync(0xffffffffu, ss, o);
    }
    __shared__ float rs[8], rss[8];
    int w = tid >> 5, lane = tid & 31;
    if (lane == 0) { rs[w] = s; rss[w] = ss; }
    __syncthreads();
    if (w == 0) {
        float a = (lane < 8) ? rs[lane] : 0.f;
        float b2 = (lane < 8) ? rss[lane] : 0.f;
        #pragma unroll
        for (int o = 4; o > 0; o >>= 1) {
            a  += __shfl_xor_sync(0xffffffffu, a, o);
            b2 += __shfl_xor_sync(0xffffffffu, b2, o);
        }
        if (lane == 0) { rs[0] = a; rss[0] = b2; }
    }
    __syncthreads();
    float mean = rs[0] * (1.f / DIMC);
    float var  = rss[0] * (1.f / DIMC) - mean * mean;
    float rstd = rsqrtf(var + 1e-5f);
    float* dst = g_ln + (size_t)row * DIMC;
    dst[tid]       = to_tf32((v0 - mean) * rstd * gamma[tid]       + beta[tid]);
    dst[tid + 256] = to_tf32((v1 - mean) * rstd * gamma[tid + 256] + beta[tid + 256]);
    dst[tid + 512] = to_tf32((v2 - mean) * rstd * gamma[tid + 512] + beta[tid + 512]);
}

// ------------------------------ temporal attention -------------------------
__global__ __launch_bounds__(256)
void temporal_attn_kernel(const float* __restrict__ qkv, float* __restrict__ out) {
    int idx = blockIdx.x * blockDim.x + threadIdx.x;
    if (idx >= (ROWS_T / TT) * NHEADS * TT) return;
    int g = idx / (NHEADS * TT);
    int rem = idx - g * (NHEADS * TT);
    int h = rem >> 2, t = rem & 3;
    size_t base = (size_t)g * TT * (3 * DIMC);
    const float4* qp = (const float4*)(qkv + base + (size_t)t * (3 * DIMC) + h * HDIM);
    float4 q[16];
    #pragma unroll
    for (int i = 0; i < 16; i++) q[i] = qp[i];
    float s[4];
    #pragma unroll
    for (int j = 0; j < 4; j++) {
        const float4* kp = (const float4*)(qkv + base + (size_t)j * (3 * DIMC) + DIMC + h * HDIM);
        float a = 0.f;
        #pragma unroll
        for (int i = 0; i < 16; i++) {
            float4 k = kp[i];
            a += q[i].x * k.x + q[i].y * k.y + q[i].z * k.z + q[i].w * k.w;
        }
        s[j] = a * 0.125f;
    }
    float m = fmaxf(fmaxf(s[0], s[1]), fmaxf(s[2], s[3]));
    float p[4], l = 0.f;
    #pragma unroll
    for (int j = 0; j < 4; j++) { p[j] = __expf(s[j] - m); l += p[j]; }
    float inv = 1.f / l;
    #pragma unroll
    for (int j = 0; j < 4; j++) p[j] *= inv;
    const float4* v0 = (const float4*)(qkv + base + 0 * (3 * DIMC) + 2 * DIMC + h * HDIM);
    const float4* v1 = (const float4*)(qkv + base + 1 * (3 * DIMC) + 2 * DIMC + h * HDIM);
    const float4* v2 = (const float4*)(qkv + base + 2 * (3 * DIMC) + 2 * DIMC + h * HDIM);
    const float4* v3 = (const float4*)(qkv + base + 3 * (3 * DIMC) + 2 * DIMC + h * HDIM);
    float4* op = (float4*)(out + ((size_t)g * TT + t) * DIMC + h * HDIM);
    #pragma unroll
    for (int i = 0; i < 16; i++) {
        float4 a = v0[i], b = v1[i], c = v2[i], d = v3[i];
        float4 o;
        o.x = to_tf32(p[0]*a.x + p[1]*b.x + p[2]*c.x + p[3]*d.x);
        o.y = to_tf32(p[0]*a.y + p[1]*b.y + p[2]*c.y + p[3]*d.y);
        o.z = to_tf32(p[0]*a.z + p[1]*b.z + p[2]*c.z + p[3]*d.z);
        o.w = to_tf32(p[0]*a.w + p[1]*b.w + p[2]*c.w + p[3]*d.w);
        op[i] = o;
    }
}

// ------------------------------ geometry bias LUT --------------------------
__global__ void bias_table_kernel(const float* __restrict__ wg_w,
                                  const float* __restrict__ wg_b) {
    int h = blockIdx.x;
    int tid = threadIdx.x;
    int dr = tid >> 5, dc = tid & 31;
    const float* w = wg_w + h * 64;
    float vx = fabsf(((float)dr / 32.0f) / 1.03125f);
    float vy = fabsf(((float)dc / 32.0f) / 1.03125f);
    float dx = logf(fmaxf(vx, 0.001f));
    float dy = logf(fmaxf(vy, 0.001f));
    float acc = wg_b[h];
    #pragma unroll
    for (int mm = 48; mm < 64; mm++) acc += w[mm];
    #pragma unroll
    for (int mm = 0; mm < 8; mm++) {
        float dm = powf(1000.0f, -(float)mm / 8.0f);
        float ax = 100.f * dx * dm;
        float ay = 100.f * dy * dm;
        acc += sinf(ax) * w[mm] + sinf(ay) * w[8 + mm]
             + cosf(ax) * w[32 + mm] + cosf(ay) * w[40 + mm];
    }
    float ww = fmaxf(acc, 0.f);
    g_btab[h * 1024 + tid] = logf(fmaxf(ww, 1e-6f));
}

// ------------------------------ spatial attention (tf32 WMMA) --------------
#define SQ_LD   72
#define SATT_Q  0
#define SATT_K  (128 * SQ_LD)
#define SATT_V  (SATT_K + 64 * SQ_LD)
#define SATT_S  (SATT_V + 64 * SQ_LD)
#define SATT_L  (SATT_S + 128 * SQ_LD)
#define SATT_SMEM ((SATT_L + 128) * 4)      // 111104 bytes
#define NKT     ((NS + 63) / 64)            // 17

__global__ __launch_bounds__(256, 2)
void spatial_attn_wmma(const float* __restrict__ qkv, float* __restrict__ out) {
    extern __shared__ float sm[];
    float* Qs = sm + SATT_Q;
    float* Ks = sm + SATT_K;
    float* Vs = sm + SATT_V;
    float* Sp = sm + SATT_S;
    float* Lw = sm + SATT_L;

    int bh = blockIdx.x;
    int bt = bh / NHEADS, h = bh - bt * NHEADS;
    int tid = threadIdx.x, wid = tid >> 5;
    int qbase = blockIdx.y * 128;

    for (int i = tid; i < 128 * 16; i += 256) {
        int r = i >> 4, c4 = (i & 15) * 4;
        int qi = qbase + r;
        float4 v = make_float4(0.f, 0.f, 0.f, 0.f);
        if (qi < NS)
            v = *(const float4*)(qkv + ((size_t)bt * NS + qi) * (3 * DIMC) + h * HDIM + c4);
        v.x *= 0.125f; v.y *= 0.125f; v.z *= 0.125f; v.w *= 0.125f;
        *(float4*)&Qs[r * SQ_LD + c4] = v;
    }
    if (tid < 128) Lw[tid] = 0.f;

    int myrow = tid >> 1;
    int mycol = (tid & 1) * 32;
    int qi_own = qbase + myrow;
    bool qvalid = qi_own < NS;
    int brow = 0, bcol = 0;
    if (qvalid && qi_own > 0) { brow = (qi_own - 1) >> 5; bcol = (qi_own - 1) & 31; }
    const float* btab_h = g_btab + h * 1024;

    wmma::fragment<wmma::accumulator, 16, 16, 8, float> oacc[4];
    #pragma unroll
    for (int j = 0; j < 4; j++) wmma::fill_fragment(oacc[j], 0.0f);

    for (int kt = 0; kt < NKT; kt++) {
        int k0 = kt * 64;
        __syncthreads();
        for (int i = tid; i < 64 * 16; i += 256) {
            int r = i >> 4, c4 = (i & 15) * 4;
            int jj = k0 + r;
            float4 kv = make_float4(0.f, 0.f, 0.f, 0.f);
            float4 vv = make_float4(0.f, 0.f, 0.f, 0.f);
            if (jj < NS) {
                const float* base = qkv + ((size_t)bt * NS + jj) * (3 * DIMC) + h * HDIM + c4;
                kv = *(const float4*)(base + DIMC);
                vv = *(const float4*)(base + 2 * DIMC);
            }
            *(float4*)&Ks[r * SQ_LD + c4] = kv;
            *(float4*)&Vs[r * SQ_LD + c4] = vv;
        }
        __syncthreads();

        // S = Q @ K^T
        {
            wmma::fragment<wmma::accumulator, 16, 16, 8, float> sacc[4];
            #pragma unroll
            for (int j = 0; j < 4; j++) wmma::fill_fragment(sacc[j], 0.0f);
            #pragma unroll
            for (int ks = 0; ks < 8; ks++) {
                wmma::fragment<wmma::matrix_a, 16, 16, 8, wmma::precision::tf32, wmma::row_major> af;
                wmma::load_matrix_sync(af, Qs + (wid * 16) * SQ_LD + ks * 8, SQ_LD);
                #pragma unroll
                for (int j = 0; j < 4; j++) {
                    wmma::fragment<wmma::matrix_b, 16, 16, 8, wmma::precision::tf32, wmma::col_major> bf;
                    wmma::load_matrix_sync(bf, Ks + (j * 16) * SQ_LD + ks * 8, SQ_LD);
                    wmma::mma_sync(sacc[j], af, bf, sacc[j]);
                }
            }
            #pragma unroll
            for (int j = 0; j < 4; j++)
                wmma::store_matrix_sync(Sp + (wid * 16) * SQ_LD + j * 16, sacc[j], SQ_LD, wmma::mem_row_major);
        }
        __syncthreads();

        // P = exp(S + bias); row-sum into Lw; P stored tf32-rounded
        {
            float* srow = Sp + myrow * SQ_LD + mycol;
            float part = 0.f;
            if (qvalid) {
                #pragma unroll
                for (int c = 0; c < 32; c++) {
                    int jj = k0 + mycol + c;
                    float p = 0.f;
                    if (jj < NS) {
                        float s = srow[c];
                        if (qi_own > 0 && jj > 0) {
                            int jr = (jj - 1) >> 5, jc = (jj - 1) & 31;
                            int dr = brow - jr; dr = dr < 0 ? -dr : dr;
                            int dc = bcol - jc; dc = dc < 0 ? -dc : dc;
                            s += __ldg(&btab_h[dr * 32 + dc]);
                        }
                        p = __expf(s);
                    }
                    srow[c] = to_tf32(p);
                    part += p;
                }
            } else {
                #pragma unroll
                for (int c = 0; c < 32; c++) srow[c] = 0.f;
            }
            part += __shfl_xor_sync(0xffffffffu, part, 1);
            if ((tid & 1) == 0) Lw[myrow] += part;
        }
        __syncthreads();

        // O += P @ V
        #pragma unroll
        for (int ks = 0; ks < 8; ks++) {
            wmma::fragment<wmma::matrix_a, 16, 16, 8, wmma::precision::tf32, wmma::row_major> af;
            wmma::load_matrix_sync(af, Sp + (wid * 16) * SQ_LD + ks * 8, SQ_LD);
            #pragma unroll
            for (int j = 0; j < 4; j++) {
                wmma::fragment<wmma::matrix_b, 16, 16, 8, wmma::precision::tf32, wmma::row_major> bf;
                wmma::load_matrix_sync(bf, Vs + (ks * 8) * SQ_LD + j * 16, SQ_LD);
                wmma::mma_sync(oacc[j], af, bf, oacc[j]);
            }
        }
    }

    __syncthreads();
    #pragma unroll
    for (int j = 0; j < 4; j++)
        wmma::store_matrix_sync(Sp + (wid * 16) * SQ_LD + j * 16, oacc[j], SQ_LD, wmma::mem_row_major);
    __syncthreads();

    if (qvalid) {
        float inv = 1.f / Lw[myrow];
        const float* srow = Sp + myrow * SQ_LD + mycol;
        float* op = out + ((size_t)bt * NS + qi_own) * DIMC + h * HDIM + mycol;
        #pragma unroll
        for (int c = 0; c < 32; c += 4) {
            float4 v = *(const float4*)(srow + c);
            v.x = to_tf32(v.x * inv); v.y = to_tf32(v.y * inv);
            v.z = to_tf32(v.z * inv); v.w = to_tf32(v.w * inv);
            *(float4*)(op + c) = v;
        }
    }
}

// ------------------------------ elementwise --------------------------------
__global__ void copy_xt_kernel(const float* __restrict__ x) {
    int idx = blockIdx.x * blockDim.x + threadIdx.x;
    if (idx >= ROWS_T * DIMC) return;
    int row = idx / DIMC, d = idx - row * DIMC;
    int b = row >> 12, j = row & 4095;
    g_xt[idx] = x[((size_t)b * NTOK + 1 + j) * DIMC + d];
}

__global__ void combine_kernel(const float* __restrict__ x, float* __restrict__ out) {
    int idx = blockIdx.x * blockDim.x + threadIdx.x;
    if (idx >= ROWS_O * DIMC) return;
    int row = idx / DIMC, d = idx - row * DIMC;
    int b = row / NTOK, tok = row - b * NTOK;
    float v;
    if (tok == 0) {
        float s = 0.f;
        #pragma unroll
        for (int t = 0; t < TT; t++)
            s += g_res[((size_t)(b * TT + t) * NS + 0) * DIMC + d];
        v = x[idx] + 0.25f * s;
    } else {
        int p = tok - 1;
        int hw = p >> 2, t = p & 3;
        v = g_xt[((size_t)b * NPATCH + p) * DIMC + d]
          + g_res[((size_t)(b * TT + t) * NS + 1 + hw) * DIMC + d];
    }
    out[idx] = v;
}

// ------------------------------ launch -------------------------------------
extern "C" void kernel_launch(void* const* d_in, const int* in_sizes, int n_in,
                              void* d_out, int out_size) {
    const float* x       = (const float*)d_in[0];
    const float* norm1_g = (const float*)d_in[1];
    const float* norm1_b = (const float*)d_in[2];
    const float* qkv_w   = (const float*)d_in[3];
    const float* proj_w  = (const float*)d_in[4];
    const float* proj_b  = (const float*)d_in[5];
    const float* wg_w    = (const float*)d_in[6];
    const float* wg_b    = (const float*)d_in[7];
    const float* tnorm1_g= (const float*)d_in[8];
    const float* tnorm1_b= (const float*)d_in[9];
    const float* tqkv_w  = (const float*)d_in[10];
    const float* tproj_w = (const float*)d_in[11];
    const float* tproj_b = (const float*)d_in[12];
    const float* tfc_w   = (const float*)d_in[13];
    const float* tfc_b   = (const float*)d_in[14];
    const float* norm2_g = (const float*)d_in[15];
    const float* norm2_b = (const float*)d_in[16];
    const float* fc1_w   = (const float*)d_in[17];
    const float* fc1_b   = (const float*)d_in[18];
    const float* fc2_w   = (const float*)d_in[19];
    const float* fc2_b   = (const float*)d_in[20];
    float* out = (float*)d_out;

    float *p_ln, *p_qkv, *p_attn, *p_res, *p_xt, *p_h, *p_wr, *p_bf;
    cudaGetSymbolAddress((void**)&p_ln,   g_ln);
    cudaGetSymbolAddress((void**)&p_qkv,  g_qkv);
    cudaGetSymbolAddress((void**)&p_attn, g_attn);
    cudaGetSymbolAddress((void**)&p_res,  g_res);
    cudaGetSymbolAddress((void**)&p_xt,   g_xt);
    cudaGetSymbolAddress((void**)&p_h,    g_h);
    cudaGetSymbolAddress((void**)&p_wr,   g_wr);
    cudaGetSymbolAddress((void**)&p_bf,   g_bf);

    cudaFuncSetAttribute(wmma_gemm<0,0,0>, cudaFuncAttributeMaxDynamicSharedMemorySize, GEMM_SMEM);
    cudaFuncSetAttribute(wmma_gemm<0,0,1>, cudaFuncAttributeMaxDynamicSharedMemorySize, GEMM_SMEM);
    cudaFuncSetAttribute(wmma_gemm<0,1,0>, cudaFuncAttributeMaxDynamicSharedMemorySize, GEMM_SMEM);
    cudaFuncSetAttribute(wmma_gemm<1,0,1>, cudaFuncAttributeMaxDynamicSharedMemorySize, GEMM_SMEM);
    cudaFuncSetAttribute(spatial_attn_wmma, cudaFuncAttributeMaxDynamicSharedMemorySize, SATT_SMEM);

    // ---- prep: round weights; fuse tfc∘tproj on tensor cores ----
    round_w_kernel<<<(1769472+255)/256, 256>>>(qkv_w,  p_wr + WR_QKV,  1769472);
    round_w_kernel<<<(1769472+255)/256, 256>>>(tqkv_w, p_wr + WR_TQKV, 1769472);
    round_w_kernel<<<(589824+255)/256, 256>>>(proj_w,  p_wr + WR_PROJ, 589824);
    round_w_kernel<<<(2359296+255)/256, 256>>>(fc1_w,  p_wr + WR_FC1,  2359296);
    round_w_kernel<<<(2359296+255)/256, 256>>>(fc2_w,  p_wr + WR_FC2,  2359296);
    // scratch in g_h (pre-fc1): [0..589824) = round(tproj_w^T), [589824..1179648) = round(tfc_w)
    transpose_round_kernel<<<dim3(24, 24), dim3(32, 8)>>>(tproj_w, p_h);
    round_w_kernel<<<(589824+255)/256, 256>>>(tfc_w, p_h + 589824, 589824);
    // F = tfc_w @ (tproj_w^T)^T : wmma_gemm(A=tfc_w, W=tproj_wT) since C = A@W^T
    wmma_gemm<0,0,1><<<dim3(6, 6), 256, GEMM_SMEM>>>(p_h + 589824, p_h, nullptr, p_wr + WR_WF, DIMC, DIMC, DIMC);
    fuse_b_kernel<<<96, 256>>>(tfc_w, tproj_b, tfc_b);

    // ---- temporal branch ----
    ln_kernel<<<ROWS_T, 256>>>(x, nullptr, tnorm1_g, tnorm1_b, 0);
    wmma_gemm<0,0,1><<<dim3(18, 64), 256, GEMM_SMEM>>>(p_ln, p_wr + WR_TQKV, nullptr, p_qkv, ROWS_T, 3*DIMC, DIMC);
    temporal_attn_kernel<<<(ROWS_T * NHEADS + 255) / 256, 256>>>(p_qkv, p_attn);
    copy_xt_kernel<<<(ROWS_T * DIMC + 255) / 256, 256>>>(x);
    wmma_gemm<0,1,0><<<dim3(6, 64), 256, GEMM_SMEM>>>(p_attn, p_wr + WR_WF, p_bf, p_xt, ROWS_T, DIMC, DIMC);

    // ---- spatial branch ----
    ln_kernel<<<ROWS_S, 256>>>(x, nullptr, norm1_g, norm1_b, 1);
    wmma_gemm<0,0,1><<<dim3(18, 65), 256, GEMM_SMEM>>>(p_ln, p_wr + WR_QKV, nullptr, p_qkv, ROWS_S, 3*DIMC, DIMC);
    bias_table_kernel<<<NHEADS, 1024>>>(wg_w, wg_b);
    spatial_attn_wmma<<<dim3(BB*TT*NHEADS, (NS + 127) / 128), 256, SATT_SMEM>>>(p_qkv, p_attn);
    wmma_gemm<0,0,0><<<dim3(6, 65), 256, GEMM_SMEM>>>(p_attn, p_wr + WR_PROJ, proj_b, p_res, ROWS_S, DIMC, DIMC);
    combine_kernel<<<(ROWS_O * DIMC + 255) / 256, 256>>>(x, out);

    // ---- MLP ----
    ln_kernel<<<ROWS_O, 256>>>(nullptr, out, norm2_g, norm2_b, 2);
    wmma_gemm<1,0,1><<<dim3(24, 65), 256, GEMM_SMEM>>>(p_ln, p_wr + WR_FC1, fc1_b, p_h, ROWS_O, MLPH, DIMC);
    wmma_gemm<0,1,0><<<dim3(6, 65), 256, GEMM_SMEM>>>(p_h, p_wr + WR_FC2, fc2_b, out, ROWS_O, DIMC, MLPH);
}